// round 12
// baseline (speedup 1.0000x reference)
#include <cuda_runtime.h>
#include <cuda_bf16.h>
#include <math.h>
#include <stdint.h>

#define B_   32
#define T_   1024
#define IN_  64
#define RES_ 2048
#define HID_ 512
#define OUT_ 64
#define BT_  (B_ * T_)
#define NCTA_ 128

typedef unsigned long long ull;

// ---- fp32x2 (readout gemm) ----
__device__ __forceinline__ void ffma2(ull& d, ull a, ull b)
{ asm("fma.rn.f32x2 %0, %1, %2, %0;" : "+l"(d) : "l"(a), "l"(b)); }
__device__ __forceinline__ ull splat2(float h)
{ ull r; asm("mov.b64 %0, {%1, %1};" : "=l"(r) : "f"(h)); return r; }
__device__ __forceinline__ void unpack2(ull v, float& lo, float& hi)
{ asm("mov.b64 {%0, %1}, %2;" : "=f"(lo), "=f"(hi) : "l"(v)); }

// ---- acq/rel flags ----
__device__ __forceinline__ unsigned ld_acq(const unsigned* p)
{ unsigned v; asm volatile("ld.acquire.gpu.global.u32 %0, [%1];" : "=r"(v) : "l"(p)); return v; }
__device__ __forceinline__ void st_rel(unsigned* p, unsigned v)
{ asm volatile("st.release.gpu.global.u32 [%0], %1;" :: "l"(p), "r"(v) : "memory"); }

// ---- warp mma bf16 m16n8k16 (baseline PTX, validated R10) ----
__device__ __forceinline__ void mma16816(float c[4], const uint32_t a[4], const uint32_t b[2])
{
    asm volatile(
        "mma.sync.aligned.m16n8k16.row.col.f32.bf16.bf16.f32 "
        "{%0,%1,%2,%3},{%4,%5,%6,%7},{%8,%9},{%0,%1,%2,%3};"
        : "+f"(c[0]), "+f"(c[1]), "+f"(c[2]), "+f"(c[3])
        : "r"(a[0]), "r"(a[1]), "r"(a[2]), "r"(a[3]), "r"(b[0]), "r"(b[1]));
}

// ---- scratch ----
__device__ float    g_UT[(size_t)T_ * RES_ * B_];
__device__ unsigned g_gh[2 * B_ * RES_];          // packed bf16 hi|lo<<16, [buf][b][k]
__device__ unsigned g_sf[1024];                   // flag[cta] @ cta*8
__device__ float    g_a1[(size_t)BT_ * HID_];
__device__ float    g_a2[(size_t)BT_ * HID_];

// ---------------- U = x @ W_in^T -> UT[t][r][b] ----------------
__global__ void __launch_bounds__(256) u_kernel(const float* __restrict__ x,
                                                const float* __restrict__ Win,
                                                float* __restrict__ UT)
{
    __shared__ float xS[IN_][B_];
    __shared__ float wS[IN_][128];
    const int t = blockIdx.y, R0 = blockIdx.x * 128, tid = threadIdx.x;
    {
        int b = tid >> 3, iq = (tid & 7) * 8;
        const float* src = x + (size_t)b * (T_ * IN_) + (size_t)t * IN_ + iq;
        float4 v0 = *(const float4*)src, v1 = *(const float4*)(src + 4);
        xS[iq+0][b]=v0.x; xS[iq+1][b]=v0.y; xS[iq+2][b]=v0.z; xS[iq+3][b]=v0.w;
        xS[iq+4][b]=v1.x; xS[iq+5][b]=v1.y; xS[iq+6][b]=v1.z; xS[iq+7][b]=v1.w;
    }
    {
        int r = tid >> 1, ih = (tid & 1) * 32;
        const float* src = Win + (size_t)(R0 + r) * IN_ + ih;
#pragma unroll
        for (int j = 0; j < 32; j += 4) {
            float4 v = *(const float4*)(src + j);
            wS[ih+j+0][r]=v.x; wS[ih+j+1][r]=v.y; wS[ih+j+2][r]=v.z; wS[ih+j+3][r]=v.w;
        }
    }
    __syncthreads();
    const int tx = tid & 7, ty = tid >> 3, b0 = tx * 4, r0 = ty * 4;
    float acc[4][4];
#pragma unroll
    for (int i = 0; i < 4; i++)
#pragma unroll
        for (int j = 0; j < 4; j++) acc[i][j] = 0.f;
#pragma unroll
    for (int i = 0; i < IN_; i++) {
        float4 xv = *(const float4*)&xS[i][b0];
        float4 wv = *(const float4*)&wS[i][r0];
        float xa[4] = {xv.x, xv.y, xv.z, xv.w}, wa[4] = {wv.x, wv.y, wv.z, wv.w};
#pragma unroll
        for (int ri = 0; ri < 4; ri++)
#pragma unroll
            for (int bi = 0; bi < 4; bi++) acc[ri][bi] = fmaf(wa[ri], xa[bi], acc[ri][bi]);
    }
    float* dst = UT + (size_t)t * (RES_ * B_);
#pragma unroll
    for (int ri = 0; ri < 4; ri++)
        *(float4*)(dst + (size_t)(R0 + r0 + ri) * B_ + b0) =
            make_float4(acc[ri][0], acc[ri][1], acc[ri][2], acc[ri][3]);
}

// ---------------- warp-MMA persistent scan, full K per CTA, ONE flag hop/step --------
// 128 CTAs x 256 threads; CTA owns rows [16*bid, 16*bid+16), K = 2048 entirely local.
// SMEM: W_hi[16][4112B] | W_lo | Bbuf[2][{hi,lo}[32][272B]] | red[2][16][36]f32
#define WROWB 4112
#define W_HI  0
#define W_LO  65792
#define BB    131584
#define BBSTR 17408
#define BROW  272
#define REDO  166400
#define SCAN_SMEM 171008

__global__ void __launch_bounds__(256) scan_mma_kernel(const float* __restrict__ Wh,
                                                       float* __restrict__ UT)
{
    extern __shared__ unsigned char smem_raw[];
    unsigned char* sw_hi = smem_raw + W_HI;
    unsigned char* sw_lo = smem_raw + W_LO;
    float* red = (float*)(smem_raw + REDO);

    const int tid  = threadIdx.x;
    const int w    = tid >> 5, lane = tid & 31;
    const int g    = lane >> 2, tq = lane & 3;
    const int nt   = w & 3;          // n-tile (8 b-values)
    const int kh   = w >> 2;         // k-half within chunk (4 k16 each)
    const int bid  = blockIdx.x;
    const int R0   = bid * 16;

    // one-time: W rows -> SMEM bf16 hi/lo  (row r, k = tid*8 .. tid*8+7)
    for (int r = 0; r < 16; r++) {
        const float* wrow = Wh + (size_t)(R0 + r) * RES_ + tid * 8;
#pragma unroll
        for (int j = 0; j < 4; j++) {
            float2 v = *(const float2*)(wrow + j * 2);
            __nv_bfloat16 h0 = __float2bfloat16(v.x), h1 = __float2bfloat16(v.y);
            __nv_bfloat16 l0 = __float2bfloat16(v.x - __bfloat162float(h0));
            __nv_bfloat16 l1 = __float2bfloat16(v.y - __bfloat162float(h1));
            unsigned hp = (unsigned)__bfloat16_as_ushort(h0) | ((unsigned)__bfloat16_as_ushort(h1) << 16);
            unsigned lp = (unsigned)__bfloat16_as_ushort(l0) | ((unsigned)__bfloat16_as_ushort(l1) << 16);
            int kbyte = (tid * 8 + j * 2) * 2;
            *(uint32_t*)(sw_hi + r * WROWB + kbyte) = hp;
            *(uint32_t*)(sw_lo + r * WROWB + kbyte) = lp;
        }
    }
    __syncthreads();

    // epilogue thread mapping (FIXED): b-col = tid & 31; rows (tid>>5)*2 + {0,1}
    const int ecol = tid & 31;           // b index, 0..31
    const int erow = (tid >> 5) * 2;     // row base, 0..14 (2 rows per thread)
    float hprev[2] = {0.f, 0.f};

    for (int t = 0; t < T_; t++) {
        const int pr = t & 1;        // gh buffer with h(t-1); h(-1) = buf0 (zeroed)
        const int pw = pr ^ 1;
        const unsigned* ghr = g_gh + (size_t)pr * (B_ * RES_);

        // ---- ONE wait site: 128 parallel raw spins on per-CTA flags ----
        if (tid < NCTA_) {
            const unsigned* fp = g_sf + tid * 8;
            while ((int)(ld_acq(fp) - (unsigned)t) < 0) {}
        }
        __syncthreads();

        float c[4] = {0.f, 0.f, 0.f, 0.f};

        // ---- stage chunk 0 ----
        auto stage = [&](int c0, int buf) {
            unsigned char* bh = smem_raw + BB + buf * BBSTR;
            unsigned char* bl = bh + 8704;
#pragma unroll
            for (int j = 0; j < 4; j++) {
                int f = tid + 256 * j;          // 1024 uint4 per chunk
                int b = f >> 5, kq = f & 31;
                uint4 pq = __ldcg((const uint4*)(ghr + (size_t)b * RES_ + c0 * 128 + kq * 4));
                unsigned h01 = __byte_perm(pq.x, pq.y, 0x5410);
                unsigned h23 = __byte_perm(pq.z, pq.w, 0x5410);
                unsigned l01 = __byte_perm(pq.x, pq.y, 0x7632);
                unsigned l23 = __byte_perm(pq.z, pq.w, 0x7632);
                *(uint2*)(bh + b * BROW + kq * 8) = make_uint2(h01, h23);
                *(uint2*)(bl + b * BROW + kq * 8) = make_uint2(l01, l23);
            }
        };
        stage(0, 0);
        __syncthreads();

        for (int ck = 0; ck < 16; ck++) {
            if (ck + 1 < 16) stage(ck + 1, (ck + 1) & 1);   // LDGs issue before mma

            const unsigned char* bh = smem_raw + BB + (ck & 1) * BBSTR;
            const unsigned char* bl = bh + 8704;
#pragma unroll
            for (int i = 0; i < 4; i++) {
                int kk = kh * 4 + i;                         // k16 index within chunk
                unsigned abase = (unsigned)g * WROWB + (unsigned)ck * 256 + kk * 32 + tq * 4;
                uint32_t ah[4], al[4], bhf[2], blf[2];
                ah[0] = *(const uint32_t*)(sw_hi + abase);
                ah[1] = *(const uint32_t*)(sw_hi + abase + 8 * WROWB);
                ah[2] = *(const uint32_t*)(sw_hi + abase + 16);
                ah[3] = *(const uint32_t*)(sw_hi + abase + 8 * WROWB + 16);
                al[0] = *(const uint32_t*)(sw_lo + abase);
                al[1] = *(const uint32_t*)(sw_lo + abase + 8 * WROWB);
                al[2] = *(const uint32_t*)(sw_lo + abase + 16);
                al[3] = *(const uint32_t*)(sw_lo + abase + 8 * WROWB + 16);
                unsigned bbase = (unsigned)(nt * 8 + g) * BROW + kk * 32 + tq * 4;
                bhf[0] = *(const uint32_t*)(bh + bbase);
                bhf[1] = *(const uint32_t*)(bh + bbase + 16);
                blf[0] = *(const uint32_t*)(bl + bbase);
                blf[1] = *(const uint32_t*)(bl + bbase + 16);
                mma16816(c, ah, bhf);
                mma16816(c, ah, blf);
                mma16816(c, al, bhf);
            }
            __syncthreads();
        }

        // ---- dump frags: red[kh][row][col] ----
#pragma unroll
        for (int i = 0; i < 4; i++) {
            int row = g + (i >> 1) * 8;
            int col = nt * 8 + tq * 2 + (i & 1);
            red[kh * 576 + row * 36 + col] = c[i];
        }
        __syncthreads();

        // ---- epilogue: 2 values per thread, 1 hop publish ----
        {
            float* utr = UT + (size_t)t * (RES_ * B_);
            unsigned* ghw = g_gh + (size_t)pw * (B_ * RES_);
            unsigned pv[2];
#pragma unroll
            for (int j = 0; j < 2; j++) {
                int row = erow + j;
                float s = red[row * 36 + ecol] + red[576 + row * 36 + ecol];
                float u = utr[(size_t)(R0 + row) * B_ + ecol];
                float hn = 0.5f * hprev[j] + 0.5f * tanhf(s + u);
                hprev[j] = hn;
                utr[(size_t)(R0 + row) * B_ + ecol] = hn;
                __nv_bfloat16 hh = __float2bfloat16(hn);
                __nv_bfloat16 ll = __float2bfloat16(hn - __bfloat162float(hh));
                pv[j] = (unsigned)__bfloat16_as_ushort(hh) |
                        ((unsigned)__bfloat16_as_ushort(ll) << 16);
            }
            __stcg((uint2*)(ghw + (size_t)ecol * RES_ + R0 + erow), make_uint2(pv[0], pv[1]));
        }
        __syncthreads();                   // epilogue reads/stores done; red reusable
        if (tid == 0) st_rel(g_sf + bid * 8, (unsigned)(t + 1));
    }
}

// ---------------- readout gemm (R7 double-buffered, fp32x2) ----------------
__device__ __forceinline__ float gelu_f(float v)
{ return 0.5f * v * (1.0f + erff(v * 0.70710678118654752f)); }

template <int A_MODE, int ACT, int OUT_MODE>
__global__ void __launch_bounds__(256) gemm_kernel(const float* __restrict__ A, int K,
                                                   const float* __restrict__ W,
                                                   const float* __restrict__ bias,
                                                   float* __restrict__ C, int ldc)
{
    __shared__ float As[2][16][132];
    __shared__ float Ws[2][16][64];
    const int m0 = blockIdx.x * 128, n0 = blockIdx.y * 64, tid = threadIdx.x;
    const int tx = tid & 15, ty = tid >> 4;

    int la_b = 0, la_kk = 0, la_tt = 0, la_mm = 0;
    if (A_MODE == 0) {
        int base = tid * 8;
        la_b = base & 31; la_kk = (base >> 5) & 15; la_tt = base >> 9;
        la_mm = la_tt * 32 + la_b;
    } else { la_mm = tid >> 1; la_kk = (tid & 1) * 8; }
    const int lw_n = tid >> 2, lw_kq = (tid & 3) * 4;
    float a_ld[8], w_ld[4];

    auto ldg_tile = [&](int k0) {
        const float* src = (A_MODE == 0)
            ? A + ((size_t)(m0 >> 5) + la_tt) * (RES_ * B_) + (size_t)(k0 + la_kk) * B_ + la_b
            : A + (size_t)(m0 + la_mm) * K + k0 + la_kk;
        float4 v0 = *(const float4*)src, v1 = *(const float4*)(src + 4);
        a_ld[0]=v0.x; a_ld[1]=v0.y; a_ld[2]=v0.z; a_ld[3]=v0.w;
        a_ld[4]=v1.x; a_ld[5]=v1.y; a_ld[6]=v1.z; a_ld[7]=v1.w;
        float4 v = *(const float4*)(W + (size_t)(n0 + lw_n) * K + k0 + lw_kq);
        w_ld[0]=v.x; w_ld[1]=v.y; w_ld[2]=v.z; w_ld[3]=v.w;
    };
    auto sts_tile = [&](int buf) {
        if (A_MODE == 0) {
            *(float4*)&As[buf][la_kk][la_mm]     = make_float4(a_ld[0], a_ld[1], a_ld[2], a_ld[3]);
            *(float4*)&As[buf][la_kk][la_mm + 4] = make_float4(a_ld[4], a_ld[5], a_ld[6], a_ld[7]);
        } else {
#pragma unroll
            for (int j = 0; j < 8; j++) As[buf][la_kk + j][la_mm] = a_ld[j];
        }
#pragma unroll
        for (int j = 0; j < 4; j++) Ws[buf][lw_kq + j][lw_n] = w_ld[j];
    };

    ull c2[4][4];
#pragma unroll
    for (int i = 0; i < 4; i++)
#pragma unroll
        for (int j = 0; j < 4; j++) c2[i][j] = 0ull;

    ldg_tile(0); sts_tile(0); __syncthreads();

    for (int k0 = 0; k0 < K; k0 += 16) {
        const int cur = (k0 >> 4) & 1;
        const bool more = (k0 + 16 < K);
        if (more) ldg_tile(k0 + 16);
#pragma unroll
        for (int kk = 0; kk < 16; kk++) {
            ulonglong2 a01 = *(const ulonglong2*)&As[cur][kk][ty * 8];
            ulonglong2 a23 = *(const ulonglong2*)&As[cur][kk][ty * 8 + 4];
            float4 wv = *(const float4*)&Ws[cur][kk][tx * 4];
            ull w0 = splat2(wv.x), w1 = splat2(wv.y), w2 = splat2(wv.z), w3 = splat2(wv.w);
            ffma2(c2[0][0], a01.x, w0); ffma2(c2[0][1], a01.x, w1);
            ffma2(c2[0][2], a01.x, w2); ffma2(c2[0][3], a01.x, w3);
            ffma2(c2[1][0], a01.y, w0); ffma2(c2[1][1], a01.y, w1);
            ffma2(c2[1][2], a01.y, w2); ffma2(c2[1][3], a01.y, w3);
            ffma2(c2[2][0], a23.x, w0); ffma2(c2[2][1], a23.x, w1);
            ffma2(c2[2][2], a23.x, w2); ffma2(c2[2][3], a23.x, w3);
            ffma2(c2[3][0], a23.y, w0); ffma2(c2[3][1], a23.y, w1);
            ffma2(c2[3][2], a23.y, w2); ffma2(c2[3][3], a23.y, w3);
        }
        if (more) { sts_tile(cur ^ 1); __syncthreads(); }
    }

    float bv[4];
#pragma unroll
    for (int j = 0; j < 4; j++) bv[j] = bias[n0 + tx * 4 + j];
#pragma unroll
    for (int ip = 0; ip < 4; ip++)
#pragma unroll
        for (int half = 0; half < 2; half++) {
            float r[4];
#pragma unroll
            for (int j = 0; j < 4; j++) {
                float lo, hi;
                unpack2(c2[ip][j], lo, hi);
                float v = (half == 0 ? lo : hi) + bv[j];
                r[j] = (ACT == 1) ? gelu_f(v) : v;
            }
            float4 v4 = make_float4(r[0], r[1], r[2], r[3]);
            int m = m0 + ty * 8 + ip * 2 + half;
            if (OUT_MODE == 0) *(float4*)(C + (size_t)m * ldc + n0 + tx * 4) = v4;
            else {
                int t = m >> 5, b = m & 31;
                *(float4*)(C + (size_t)b * (T_ * OUT_) + (size_t)t * OUT_ + tx * 4) = v4;
            }
        }
}

__global__ void hn_kernel(const float* __restrict__ hT, float* __restrict__ out)
{
    int i = blockIdx.x * 256 + threadIdx.x;
    int r = i >> 5, b = i & 31;
    out[(size_t)b * RES_ + r] = hT[i];
}

extern "C" void kernel_launch(void* const* d_in, const int* in_sizes, int n_in,
                              void* d_out, int out_size)
{
    const float* x   = (const float*)d_in[0];
    const float* Win = (const float*)d_in[1];
    const float* Wh  = (const float*)d_in[2];
    const float* W0  = (const float*)d_in[3];
    const float* b0  = (const float*)d_in[4];
    const float* W1  = (const float*)d_in[5];
    const float* b1  = (const float*)d_in[6];
    const float* W2  = (const float*)d_in[7];
    const float* b2  = (const float*)d_in[8];
    float*       out = (float*)d_out;

    float *UT, *a1, *a2;
    unsigned *gh, *sf;
    cudaGetSymbolAddress((void**)&UT, g_UT);
    cudaGetSymbolAddress((void**)&a1, g_a1);
    cudaGetSymbolAddress((void**)&a2, g_a2);
    cudaGetSymbolAddress((void**)&gh, g_gh);
    cudaGetSymbolAddress((void**)&sf, g_sf);

    cudaFuncSetAttribute(scan_mma_kernel, cudaFuncAttributeMaxDynamicSharedMemorySize, SCAN_SMEM);

    u_kernel<<<dim3(16, 1024), 256>>>(x, Win, UT);
    cudaMemsetAsync(gh, 0, 2ull * B_ * RES_ * sizeof(unsigned));   // h(-1) = 0
    cudaMemsetAsync(sf, 0, 1024 * sizeof(unsigned));               // flags reset per replay

    scan_mma_kernel<<<NCTA_, 256, SCAN_SMEM>>>(Wh, UT);

    gemm_kernel<0, 1, 0><<<dim3(BT_ / 128, HID_ / 64), 256>>>(UT, RES_, W0, b0, a1, HID_);
    gemm_kernel<1, 1, 0><<<dim3(BT_ / 128, HID_ / 64), 256>>>(a1, HID_, W1, b1, a2, HID_);
    gemm_kernel<1, 0, 1><<<dim3(BT_ / 128, 1), 256>>>(a2, HID_, W2, b2, out, OUT_);

    if (out_size >= (int)((size_t)B_ * T_ * OUT_ + (size_t)B_ * RES_))
        hn_kernel<<<RES_ * B_ / 256, 256>>>(UT + (size_t)(T_ - 1) * (RES_ * B_),
                                            out + (size_t)B_ * T_ * OUT_);
}

// round 13
// speedup vs baseline: 1.4757x; 1.4757x over previous
#include <cuda_runtime.h>
#include <cuda_bf16.h>
#include <math.h>
#include <stdint.h>

#define B_   32
#define T_   1024
#define IN_  64
#define RES_ 2048
#define HID_ 512
#define OUT_ 64
#define BT_  (B_ * T_)
#define NCTA_ 128

typedef unsigned long long ull;

// ---- fp32x2 (readout gemm) ----
__device__ __forceinline__ void ffma2(ull& d, ull a, ull b)
{ asm("fma.rn.f32x2 %0, %1, %2, %0;" : "+l"(d) : "l"(a), "l"(b)); }
__device__ __forceinline__ ull splat2(float h)
{ ull r; asm("mov.b64 %0, {%1, %1};" : "=l"(r) : "f"(h)); return r; }
__device__ __forceinline__ void unpack2(ull v, float& lo, float& hi)
{ asm("mov.b64 {%0, %1}, %2;" : "=f"(lo), "=f"(hi) : "l"(v)); }

// ---- acq/rel flags ----
__device__ __forceinline__ unsigned ld_acq(const unsigned* p)
{ unsigned v; asm volatile("ld.acquire.gpu.global.u32 %0, [%1];" : "=r"(v) : "l"(p)); return v; }
__device__ __forceinline__ void st_rel(unsigned* p, unsigned v)
{ asm volatile("st.release.gpu.global.u32 [%0], %1;" :: "l"(p), "r"(v) : "memory"); }

// ---- cp.async (Ampere-baseline, OK at sm_100 target) ----
__device__ __forceinline__ void cp16(uint32_t saddr, const void* g)
{ asm volatile("cp.async.cg.shared.global [%0], [%1], 16;" :: "r"(saddr), "l"(g) : "memory"); }
#define CP_COMMIT() asm volatile("cp.async.commit_group;" ::: "memory")
template <int N> __device__ __forceinline__ void cp_wait()
{ asm volatile("cp.async.wait_group %0;" :: "n"(N) : "memory"); }

// ---- warp mma bf16 m16n8k16 (validated R10/R12) ----
__device__ __forceinline__ void mma16816(float c[4], const uint32_t a[4], const uint32_t b[2])
{
    asm volatile(
        "mma.sync.aligned.m16n8k16.row.col.f32.bf16.bf16.f32 "
        "{%0,%1,%2,%3},{%4,%5,%6,%7},{%8,%9},{%0,%1,%2,%3};"
        : "+f"(c[0]), "+f"(c[1]), "+f"(c[2]), "+f"(c[3])
        : "r"(a[0]), "r"(a[1]), "r"(a[2]), "r"(a[3]), "r"(b[0]), "r"(b[1]));
}

// ---- scratch ----
__device__ float          g_UT[(size_t)T_ * RES_ * B_];
__device__ __nv_bfloat16  g_hi[2ull * B_ * RES_];   // h hi, [buf][b][k]
__device__ __nv_bfloat16  g_lo[2ull * B_ * RES_];   // h lo residual
__device__ unsigned       g_sf[1024];               // flag[cta] @ cta*8
__device__ float          g_a1[(size_t)BT_ * HID_];
__device__ float          g_a2[(size_t)BT_ * HID_];

// ---------------- U = x @ W_in^T -> UT[t][r][b] ----------------
__global__ void __launch_bounds__(256) u_kernel(const float* __restrict__ x,
                                                const float* __restrict__ Win,
                                                float* __restrict__ UT)
{
    __shared__ float xS[IN_][B_];
    __shared__ float wS[IN_][128];
    const int t = blockIdx.y, R0 = blockIdx.x * 128, tid = threadIdx.x;
    {
        int b = tid >> 3, iq = (tid & 7) * 8;
        const float* src = x + (size_t)b * (T_ * IN_) + (size_t)t * IN_ + iq;
        float4 v0 = *(const float4*)src, v1 = *(const float4*)(src + 4);
        xS[iq+0][b]=v0.x; xS[iq+1][b]=v0.y; xS[iq+2][b]=v0.z; xS[iq+3][b]=v0.w;
        xS[iq+4][b]=v1.x; xS[iq+5][b]=v1.y; xS[iq+6][b]=v1.z; xS[iq+7][b]=v1.w;
    }
    {
        int r = tid >> 1, ih = (tid & 1) * 32;
        const float* src = Win + (size_t)(R0 + r) * IN_ + ih;
#pragma unroll
        for (int j = 0; j < 32; j += 4) {
            float4 v = *(const float4*)(src + j);
            wS[ih+j+0][r]=v.x; wS[ih+j+1][r]=v.y; wS[ih+j+2][r]=v.z; wS[ih+j+3][r]=v.w;
        }
    }
    __syncthreads();
    const int tx = tid & 7, ty = tid >> 3, b0 = tx * 4, r0 = ty * 4;
    float acc[4][4];
#pragma unroll
    for (int i = 0; i < 4; i++)
#pragma unroll
        for (int j = 0; j < 4; j++) acc[i][j] = 0.f;
#pragma unroll
    for (int i = 0; i < IN_; i++) {
        float4 xv = *(const float4*)&xS[i][b0];
        float4 wv = *(const float4*)&wS[i][r0];
        float xa[4] = {xv.x, xv.y, xv.z, xv.w}, wa[4] = {wv.x, wv.y, wv.z, wv.w};
#pragma unroll
        for (int ri = 0; ri < 4; ri++)
#pragma unroll
            for (int bi = 0; bi < 4; bi++) acc[ri][bi] = fmaf(wa[ri], xa[bi], acc[ri][bi]);
    }
    float* dst = UT + (size_t)t * (RES_ * B_);
#pragma unroll
    for (int ri = 0; ri < 4; ri++)
        *(float4*)(dst + (size_t)(R0 + r0 + ri) * B_ + b0) =
            make_float4(acc[ri][0], acc[ri][1], acc[ri][2], acc[ri][3]);
}

// ---------------- warp-MMA persistent scan, cp.async pipelined h broadcast ----------
// 128 CTAs x 256 threads; CTA owns rows [16*bid, 16*bid+16), full K=2048 local.
// SMEM: W_hi[16][4112] | W_lo | 4 x Bbuf{hi[32][272], lo[32][272]} | red[2][16][36]f32
#define WROWB 4112
#define W_HI  0
#define W_LO  65792
#define BB    131584
#define BBSTR 17408
#define BROW  272
#define REDO  201216
#define SCAN_SMEM 205824

__global__ void __launch_bounds__(256) scan_mma_kernel(const float* __restrict__ Wh,
                                                       float* __restrict__ UT)
{
    extern __shared__ unsigned char smem_raw[];
    unsigned char* sw_hi = smem_raw + W_HI;
    unsigned char* sw_lo = smem_raw + W_LO;
    float* red = (float*)(smem_raw + REDO);
    const uint32_t sbase = (uint32_t)__cvta_generic_to_shared(smem_raw);

    const int tid  = threadIdx.x;
    const int w    = tid >> 5, lane = tid & 31;
    const int g    = lane >> 2, tq = lane & 3;
    const int nt   = w & 3;          // n-tile (8 b-values)
    const int kh   = w >> 2;         // k-half within chunk (4 k16 each)
    const int bid  = blockIdx.x;
    const int R0   = bid * 16;

    // one-time: W rows -> SMEM bf16 hi/lo
    for (int r = 0; r < 16; r++) {
        const float* wrow = Wh + (size_t)(R0 + r) * RES_ + tid * 8;
#pragma unroll
        for (int j = 0; j < 4; j++) {
            float2 v = *(const float2*)(wrow + j * 2);
            __nv_bfloat16 h0 = __float2bfloat16(v.x), h1 = __float2bfloat16(v.y);
            __nv_bfloat16 l0 = __float2bfloat16(v.x - __bfloat162float(h0));
            __nv_bfloat16 l1 = __float2bfloat16(v.y - __bfloat162float(h1));
            unsigned hp = (unsigned)__bfloat16_as_ushort(h0) | ((unsigned)__bfloat16_as_ushort(h1) << 16);
            unsigned lp = (unsigned)__bfloat16_as_ushort(l0) | ((unsigned)__bfloat16_as_ushort(l1) << 16);
            int kbyte = (tid * 8 + j * 2) * 2;
            *(uint32_t*)(sw_hi + r * WROWB + kbyte) = hp;
            *(uint32_t*)(sw_lo + r * WROWB + kbyte) = lp;
        }
    }
    __syncthreads();

    // epilogue mapping: b-col = tid & 31; rows (tid>>5)*2 + {0,1}
    const int ecol = tid & 31;
    const int erow = (tid >> 5) * 2;
    float hprev[2] = {0.f, 0.f};

    // per-thread cp.async source/dest indices: idx = tid*2 + i -> (row, seg)
    const int sr0 = (tid * 2) >> 4,     sg0 = (tid * 2) & 15;
    const int sr1 = (tid * 2 + 1) >> 4, sg1 = (tid * 2 + 1) & 15;

    for (int t = 0; t < T_; t++) {
        const int pr = t & 1;        // buffers with h(t-1); h(-1)=buf0 (zeroed)
        const int pw = pr ^ 1;
        const __nv_bfloat16* ghi = g_hi + (size_t)pr * (B_ * RES_);
        const __nv_bfloat16* glo = g_lo + (size_t)pr * (B_ * RES_);

        // ---- ONE wait site: 128 parallel polls ----
        if (tid < NCTA_) {
            const unsigned* fp = g_sf + tid * 8;
            while ((int)(ld_acq(fp) - (unsigned)t) < 0) __nanosleep(32);
        }
        __syncthreads();

        // ---- stage issue: chunk ck -> buf ck&3, pure cp.async (no reg wait) ----
        auto stage = [&](int ck) {
            uint32_t bh = sbase + BB + (uint32_t)(ck & 3) * BBSTR;
            uint32_t bl = bh + 8704;
            const __nv_bfloat16* s0h = ghi + (size_t)sr0 * RES_ + ck * 128 + sg0 * 8;
            const __nv_bfloat16* s0l = glo + (size_t)sr0 * RES_ + ck * 128 + sg0 * 8;
            const __nv_bfloat16* s1h = ghi + (size_t)sr1 * RES_ + ck * 128 + sg1 * 8;
            const __nv_bfloat16* s1l = glo + (size_t)sr1 * RES_ + ck * 128 + sg1 * 8;
            cp16(bh + sr0 * BROW + sg0 * 16, s0h);
            cp16(bl + sr0 * BROW + sg0 * 16, s0l);
            cp16(bh + sr1 * BROW + sg1 * 16, s1h);
            cp16(bl + sr1 * BROW + sg1 * 16, s1l);
            CP_COMMIT();
        };

        float c[4] = {0.f, 0.f, 0.f, 0.f};
        stage(0); stage(1); stage(2);

        for (int ck = 0; ck < 16; ck++) {
            if (ck <= 13) cp_wait<2>(); else if (ck == 14) cp_wait<1>(); else cp_wait<0>();
            __syncthreads();                       // chunk ck resident for all threads
            if (ck + 3 < 16) stage(ck + 3);        // refill (buf freed by barrier above)

            const unsigned char* bh = smem_raw + BB + (ck & 3) * BBSTR;
            const unsigned char* bl = bh + 8704;
#pragma unroll
            for (int i = 0; i < 4; i++) {
                int kk = kh * 4 + i;
                unsigned abase = (unsigned)g * WROWB + (unsigned)ck * 256 + kk * 32 + tq * 4;
                uint32_t ah[4], al[4], bhf[2], blf[2];
                ah[0] = *(const uint32_t*)(sw_hi + abase);
                ah[1] = *(const uint32_t*)(sw_hi + abase + 8 * WROWB);
                ah[2] = *(const uint32_t*)(sw_hi + abase + 16);
                ah[3] = *(const uint32_t*)(sw_hi + abase + 8 * WROWB + 16);
                al[0] = *(const uint32_t*)(sw_lo + abase);
                al[1] = *(const uint32_t*)(sw_lo + abase + 8 * WROWB);
                al[2] = *(const uint32_t*)(sw_lo + abase + 16);
                al[3] = *(const uint32_t*)(sw_lo + abase + 8 * WROWB + 16);
                unsigned bbase = (unsigned)(nt * 8 + g) * BROW + kk * 32 + tq * 4;
                bhf[0] = *(const uint32_t*)(bh + bbase);
                bhf[1] = *(const uint32_t*)(bh + bbase + 16);
                blf[0] = *(const uint32_t*)(bl + bbase);
                blf[1] = *(const uint32_t*)(bl + bbase + 16);
                mma16816(c, ah, bhf);
                mma16816(c, ah, blf);
                mma16816(c, al, bhf);
            }
        }

        // ---- frag dump ----
        __syncthreads();
#pragma unroll
        for (int i = 0; i < 4; i++) {
            int row = g + (i >> 1) * 8;
            int col = nt * 8 + tq * 2 + (i & 1);
            red[kh * 576 + row * 36 + col] = c[i];
        }
        __syncthreads();

        // ---- epilogue: 2 values/thread, publish hi/lo, 1 hop ----
        {
            float* utr = UT + (size_t)t * (RES_ * B_);
            __nv_bfloat16* whi = g_hi + (size_t)pw * (B_ * RES_);
            __nv_bfloat16* wlo = g_lo + (size_t)pw * (B_ * RES_);
            unsigned hv = 0, lv = 0;
#pragma unroll
            for (int j = 0; j < 2; j++) {
                int row = erow + j;
                float s = red[row * 36 + ecol] + red[576 + row * 36 + ecol];
                float u = utr[(size_t)(R0 + row) * B_ + ecol];
                float hn = 0.5f * hprev[j] + 0.5f * tanhf(s + u);
                hprev[j] = hn;
                utr[(size_t)(R0 + row) * B_ + ecol] = hn;
                __nv_bfloat16 hh = __float2bfloat16(hn);
                __nv_bfloat16 ll = __float2bfloat16(hn - __bfloat162float(hh));
                hv |= (unsigned)__bfloat16_as_ushort(hh) << (16 * j);
                lv |= (unsigned)__bfloat16_as_ushort(ll) << (16 * j);
            }
            size_t koff = (size_t)ecol * RES_ + R0 + erow;   // erow even -> 4B aligned
            __stcg((unsigned*)(whi + koff), hv);
            __stcg((unsigned*)(wlo + koff), lv);
        }
        __syncthreads();
        if (tid == 0) st_rel(g_sf + bid * 8, (unsigned)(t + 1));
    }
}

// ---------------- readout gemm (R7 double-buffered, fp32x2) ----------------
__device__ __forceinline__ float gelu_f(float v)
{ return 0.5f * v * (1.0f + erff(v * 0.70710678118654752f)); }

template <int A_MODE, int ACT, int OUT_MODE>
__global__ void __launch_bounds__(256) gemm_kernel(const float* __restrict__ A, int K,
                                                   const float* __restrict__ W,
                                                   const float* __restrict__ bias,
                                                   float* __restrict__ C, int ldc)
{
    __shared__ float As[2][16][132];
    __shared__ float Ws[2][16][64];
    const int m0 = blockIdx.x * 128, n0 = blockIdx.y * 64, tid = threadIdx.x;
    const int tx = tid & 15, ty = tid >> 4;

    int la_b = 0, la_kk = 0, la_tt = 0, la_mm = 0;
    if (A_MODE == 0) {
        int base = tid * 8;
        la_b = base & 31; la_kk = (base >> 5) & 15; la_tt = base >> 9;
        la_mm = la_tt * 32 + la_b;
    } else { la_mm = tid >> 1; la_kk = (tid & 1) * 8; }
    const int lw_n = tid >> 2, lw_kq = (tid & 3) * 4;
    float a_ld[8], w_ld[4];

    auto ldg_tile = [&](int k0) {
        const float* src = (A_MODE == 0)
            ? A + ((size_t)(m0 >> 5) + la_tt) * (RES_ * B_) + (size_t)(k0 + la_kk) * B_ + la_b
            : A + (size_t)(m0 + la_mm) * K + k0 + la_kk;
        float4 v0 = *(const float4*)src, v1 = *(const float4*)(src + 4);
        a_ld[0]=v0.x; a_ld[1]=v0.y; a_ld[2]=v0.z; a_ld[3]=v0.w;
        a_ld[4]=v1.x; a_ld[5]=v1.y; a_ld[6]=v1.z; a_ld[7]=v1.w;
        float4 v = *(const float4*)(W + (size_t)(n0 + lw_n) * K + k0 + lw_kq);
        w_ld[0]=v.x; w_ld[1]=v.y; w_ld[2]=v.z; w_ld[3]=v.w;
    };
    auto sts_tile = [&](int buf) {
        if (A_MODE == 0) {
            *(float4*)&As[buf][la_kk][la_mm]     = make_float4(a_ld[0], a_ld[1], a_ld[2], a_ld[3]);
            *(float4*)&As[buf][la_kk][la_mm + 4] = make_float4(a_ld[4], a_ld[5], a_ld[6], a_ld[7]);
        } else {
#pragma unroll
            for (int j = 0; j < 8; j++) As[buf][la_kk + j][la_mm] = a_ld[j];
        }
#pragma unroll
        for (int j = 0; j < 4; j++) Ws[buf][lw_kq + j][lw_n] = w_ld[j];
    };

    ull c2[4][4];
#pragma unroll
    for (int i = 0; i < 4; i++)
#pragma unroll
        for (int j = 0; j < 4; j++) c2[i][j] = 0ull;

    ldg_tile(0); sts_tile(0); __syncthreads();

    for (int k0 = 0; k0 < K; k0 += 16) {
        const int cur = (k0 >> 4) & 1;
        const bool more = (k0 + 16 < K);
        if (more) ldg_tile(k0 + 16);
#pragma unroll
        for (int kk = 0; kk < 16; kk++) {
            ulonglong2 a01 = *(const ulonglong2*)&As[cur][kk][ty * 8];
            ulonglong2 a23 = *(const ulonglong2*)&As[cur][kk][ty * 8 + 4];
            float4 wv = *(const float4*)&Ws[cur][kk][tx * 4];
            ull w0 = splat2(wv.x), w1 = splat2(wv.y), w2 = splat2(wv.z), w3 = splat2(wv.w);
            ffma2(c2[0][0], a01.x, w0); ffma2(c2[0][1], a01.x, w1);
            ffma2(c2[0][2], a01.x, w2); ffma2(c2[0][3], a01.x, w3);
            ffma2(c2[1][0], a01.y, w0); ffma2(c2[1][1], a01.y, w1);
            ffma2(c2[1][2], a01.y, w2); ffma2(c2[1][3], a01.y, w3);
            ffma2(c2[2][0], a23.x, w0); ffma2(c2[2][1], a23.x, w1);
            ffma2(c2[2][2], a23.x, w2); ffma2(c2[2][3], a23.x, w3);
            ffma2(c2[3][0], a23.y, w0); ffma2(c2[3][1], a23.y, w1);
            ffma2(c2[3][2], a23.y, w2); ffma2(c2[3][3], a23.y, w3);
        }
        if (more) { sts_tile(cur ^ 1); __syncthreads(); }
    }

    float bv[4];
#pragma unroll
    for (int j = 0; j < 4; j++) bv[j] = bias[n0 + tx * 4 + j];
#pragma unroll
    for (int ip = 0; ip < 4; ip++)
#pragma unroll
        for (int half = 0; half < 2; half++) {
            float r[4];
#pragma unroll
            for (int j = 0; j < 4; j++) {
                float lo, hi;
                unpack2(c2[ip][j], lo, hi);
                float v = (half == 0 ? lo : hi) + bv[j];
                r[j] = (ACT == 1) ? gelu_f(v) : v;
            }
            float4 v4 = make_float4(r[0], r[1], r[2], r[3]);
            int m = m0 + ty * 8 + ip * 2 + half;
            if (OUT_MODE == 0) *(float4*)(C + (size_t)m * ldc + n0 + tx * 4) = v4;
            else {
                int t = m >> 5, b = m & 31;
                *(float4*)(C + (size_t)b * (T_ * OUT_) + (size_t)t * OUT_ + tx * 4) = v4;
            }
        }
}

__global__ void hn_kernel(const float* __restrict__ hT, float* __restrict__ out)
{
    int i = blockIdx.x * 256 + threadIdx.x;
    int r = i >> 5, b = i & 31;
    out[(size_t)b * RES_ + r] = hT[i];
}

extern "C" void kernel_launch(void* const* d_in, const int* in_sizes, int n_in,
                              void* d_out, int out_size)
{
    const float* x   = (const float*)d_in[0];
    const float* Win = (const float*)d_in[1];
    const float* Wh  = (const float*)d_in[2];
    const float* W0  = (const float*)d_in[3];
    const float* b0  = (const float*)d_in[4];
    const float* W1  = (const float*)d_in[5];
    const float* b1  = (const float*)d_in[6];
    const float* W2  = (const float*)d_in[7];
    const float* b2  = (const float*)d_in[8];
    float*       out = (float*)d_out;

    float *UT, *a1, *a2;
    void *hi, *lo;
    unsigned* sf;
    cudaGetSymbolAddress((void**)&UT, g_UT);
    cudaGetSymbolAddress((void**)&a1, g_a1);
    cudaGetSymbolAddress((void**)&a2, g_a2);
    cudaGetSymbolAddress(&hi, g_hi);
    cudaGetSymbolAddress(&lo, g_lo);
    cudaGetSymbolAddress((void**)&sf, g_sf);

    cudaFuncSetAttribute(scan_mma_kernel, cudaFuncAttributeMaxDynamicSharedMemorySize, SCAN_SMEM);

    u_kernel<<<dim3(16, 1024), 256>>>(x, Win, UT);
    cudaMemsetAsync(hi, 0, 2ull * B_ * RES_ * sizeof(__nv_bfloat16));   // h(-1) = 0
    cudaMemsetAsync(lo, 0, 2ull * B_ * RES_ * sizeof(__nv_bfloat16));
    cudaMemsetAsync(sf, 0, 1024 * sizeof(unsigned));                    // flags reset per replay

    scan_mma_kernel<<<NCTA_, 256, SCAN_SMEM>>>(Wh, UT);

    gemm_kernel<0, 1, 0><<<dim3(BT_ / 128, HID_ / 64), 256>>>(UT, RES_, W0, b0, a1, HID_);
    gemm_kernel<1, 1, 0><<<dim3(BT_ / 128, HID_ / 64), 256>>>(a1, HID_, W1, b1, a2, HID_);
    gemm_kernel<1, 0, 1><<<dim3(BT_ / 128, 1), 256>>>(a2, HID_, W2, b2, out, OUT_);

    if (out_size >= (int)((size_t)B_ * T_ * OUT_ + (size_t)B_ * RES_))
        hn_kernel<<<RES_ * B_ / 256, 256>>>(UT + (size_t)(T_ - 1) * (RES_ * B_),
                                            out + (size_t)B_ * T_ * OUT_);
}